// round 9
// baseline (speedup 1.0000x reference)
#include <cuda_runtime.h>
#include <stdint.h>

#define Ss 2048
#define Dh 256

__device__ float g_W2[256 * 256];
__device__ __align__(16) unsigned char g_qimg[8 * 32 * 65536];  // A-frag images, 64-row tiles
__device__ __align__(16) unsigned char g_kimg[8 * 64 * 32768];  // B-frag images, 32-key tiles
__device__ __align__(16) unsigned char g_eimg[8 * 64 * 32768];  // B-frag images, 32-key tiles
__device__ __align__(16) unsigned char g_wimg[8 * 32768];       // B-frag images, 32-j chunks

// ---------------- helpers ----------------
__device__ __forceinline__ uint32_t smem_u32(const void* p) {
    uint32_t a; asm("{.reg .u64 t; cvta.to.shared.u64 t,%1; cvt.u32.u64 %0,t;}" : "=r"(a) : "l"(p)); return a;
}
__device__ __forceinline__ uint32_t tf32r(float x) {
    uint32_t r; asm("cvt.rna.tf32.f32 %0,%1;" : "=r"(r) : "f"(x)); return r;
}
__device__ __forceinline__ void mmat(float* c, const uint32_t* a, const uint32_t* b) {
    asm volatile("mma.sync.aligned.m16n8k8.row.col.f32.tf32.tf32.f32 "
        "{%0,%1,%2,%3},{%4,%5,%6,%7},{%8,%9},{%0,%1,%2,%3};"
        : "+f"(c[0]), "+f"(c[1]), "+f"(c[2]), "+f"(c[3])
        : "r"(a[0]), "r"(a[1]), "r"(a[2]), "r"(a[3]), "r"(b[0]), "r"(b[1]));
}
__device__ __forceinline__ float expclip(float s) {
    return __expf(fminf(fmaxf(s * 0.0625f, -10.f), 10.f));
}
__device__ __forceinline__ void cpa16(uint32_t dst, const void* src) {
    asm volatile("cp.async.cg.shared.global [%0],[%1],16;" :: "r"(dst), "l"(src));
}
#define CP_COMMIT() asm volatile("cp.async.commit_group;" ::: "memory")
#define CP_WAIT0()  asm volatile("cp.async.wait_group 0;" ::: "memory")
#define CP_WAIT2()  asm volatile("cp.async.wait_group 2;" ::: "memory")
#define CP_WAIT3()  asm volatile("cp.async.wait_group 3;" ::: "memory")

__device__ __forceinline__ void load32k(uint32_t dst, const unsigned char* src, int tid) {
#pragma unroll
    for (int i = 0; i < 8; i++)
        cpa16(dst + (uint32_t)(tid + 256 * i) * 16, src + (size_t)(tid + 256 * i) * 16);
}

// ---------------- prologue kernels ----------------
__global__ void wt_kernel(const float* __restrict__ W_o) {
    int j = blockIdx.x, dout = threadIdx.x;
    float s = 0.f;
#pragma unroll
    for (int h = 0; h < 8; h++) s += W_o[(size_t)dout * 2048 + h * 256 + j];
    g_W2[j * 256 + dout] = s;
}
// Q: A-frag image per 64-row q-tile: [mblk 0..3][s 0..31][lane][4]
__global__ void qimg_kernel(const float* __restrict__ p) {
    int qt = blockIdx.x, b = blockIdx.y, tid = threadIdx.x;
    const float* P = p + (size_t)b * (Ss + 1) * Dh;
    uint4* dst = (uint4*)(g_qimg + (size_t)(b * 32 + qt) * 65536);
#pragma unroll
    for (int it = 0; it < 16; it++) {
        int idx = tid + 256 * it;
        int mblk = idx >> 10, rem = idx & 1023, s = rem >> 5, l = rem & 31;
        int r = qt * 64 + mblk * 16 + (l >> 2) + 1;   // +1: q = p[:,1:,:]
        int c = 8 * s + (l & 3);
        uint4 v;
        v.x = tf32r(P[(size_t)r * Dh + c]);
        v.y = tf32r(P[(size_t)(r + 8) * Dh + c]);
        v.z = tf32r(P[(size_t)r * Dh + c + 4]);
        v.w = tf32r(P[(size_t)(r + 8) * Dh + c + 4]);
        dst[idx] = v;
    }
}
// K: B-frag image per 32-key tile: [s 0..31][nt 0..3][lane][2]   (k-dim = d)
__global__ void kimg_kernel(const float* __restrict__ p) {
    int kt = blockIdx.x, b = blockIdx.y, tid = threadIdx.x;
    const float* P = p + (size_t)b * (Ss + 1) * Dh;
    uint2* dst = (uint2*)(g_kimg + (size_t)(b * 64 + kt) * 32768);
#pragma unroll
    for (int it = 0; it < 16; it++) {
        int idx = tid + 256 * it;
        int s = idx >> 7, rem = idx & 127, nt = rem >> 5, l = rem & 31;
        int key = kt * 32 + nt * 8 + (l >> 2);
        int d = 8 * s + (l & 3);
        dst[idx] = make_uint2(tf32r(P[(size_t)key * Dh + d]), tf32r(P[(size_t)key * Dh + d + 4]));
    }
}
// E: B-frag image per 32-key tile: [s 0..3][nt 0..31][lane][2]   (k-dim = key)
__global__ void eimg_kernel(const float* __restrict__ e) {
    int kt = blockIdx.x, b = blockIdx.y, tid = threadIdx.x;
    const float* E = e + (size_t)b * Ss * Dh;
    uint2* dst = (uint2*)(g_eimg + (size_t)(b * 64 + kt) * 32768);
#pragma unroll
    for (int it = 0; it < 16; it++) {
        int idx = tid + 256 * it;
        int s = idx >> 10, rem = idx & 1023, nt = rem >> 5, l = rem & 31;
        int key = kt * 32 + 8 * s + (l & 3);
        int n = nt * 8 + (l >> 2);
        dst[idx] = make_uint2(tf32r(E[(size_t)key * Dh + n]), tf32r(E[(size_t)(key + 4) * Dh + n]));
    }
}
// W: B-frag image per 32-j chunk: [s 0..3][nt 0..31][lane][2]   (k-dim = j)
__global__ void wimg_kernel() {
    int ch = blockIdx.x, tid = threadIdx.x;
    uint2* dst = (uint2*)(g_wimg + (size_t)ch * 32768);
#pragma unroll
    for (int it = 0; it < 16; it++) {
        int idx = tid + 256 * it;
        int s = idx >> 10, rem = idx & 1023, nt = rem >> 5, l = rem & 31;
        int j = 32 * ch + 8 * s + (l & 3);
        int n = nt * 8 + (l >> 2);
        dst[idx] = make_uint2(tf32r(g_W2[j * 256 + n]), tf32r(g_W2[(j + 4) * 256 + n]));
    }
}

// ---------------- main kernel ----------------
// smem layout (bytes)
#define SY   0u        // ynorm raw [64][260] f32 (66560); Q image (65536) lives here in loop
#define SK0  66560u
#define SK1  99328u
#define SE0  132096u
#define SE1  164864u
#define SP   197632u   // P [64 rows][36 f32] = 9216
#define SDEN 206848u   // [2][64] f32
#define SMEM_BYTES 207360u

__global__ __launch_bounds__(256, 1) void attn_kernel(float* __restrict__ out) {
    extern __shared__ unsigned char smp[];
    const uint32_t sb = smem_u32(smp);
    const int tid = threadIdx.x, w = tid >> 5, l = tid & 31;
    const int tig = l & 3, gid = l >> 2;
    const int qt = 31 - (int)blockIdx.x, b = blockIdx.y;
    const int q0 = qt * 64, cnt = 2 * qt + 2;
    const int mblk = w & 3, h = w >> 2;

    const unsigned char* kim = g_kimg + (size_t)(b * 64) * 32768;
    const unsigned char* eim = g_eimg + (size_t)(b * 64) * 32768;
    const uint32_t kbuf[2] = { sb + SK0, sb + SK1 };
    const uint32_t ebuf[2] = { sb + SE0, sb + SE1 };

    // prologue loads: [Q + K0], [E0], [K1]
    {
        const unsigned char* qsrc = g_qimg + (size_t)(b * 32 + qt) * 65536;
#pragma unroll
        for (int i = 0; i < 16; i++)
            cpa16(sb + SY + (uint32_t)(tid + 256 * i) * 16, qsrc + (size_t)(tid + 256 * i) * 16);
        load32k(kbuf[0], kim, tid); CP_COMMIT();
        load32k(ebuf[0], eim, tid); CP_COMMIT();
        load32k(kbuf[1], kim + 32768, tid); CP_COMMIT();
    }

    // per-warp address bases
    const uint32_t qbase = sb + SY + (uint32_t)(mblk * 32) * 512 + l * 16;          // + s*512
    const uint32_t kfoff = (uint32_t)(2 * h) * 256 + l * 8;                          // + s*1024 + j*256
    const uint32_t efoff = (uint32_t)(16 * h) * 256 + l * 8;                         // + s*8192 + ntl*256
    const uint32_t prow = (uint32_t)(mblk * 16 + gid);
    const uint32_t pbase = sb + SP + (prow * 36 + tig) * 4;                           // + (8s+col)*4

    float yacc[16][4];
#pragma unroll
    for (int nt = 0; nt < 16; nt++)
#pragma unroll
        for (int j = 0; j < 4; j++) yacc[nt][j] = 0.f;
    float d0 = 0.f, d1 = 0.f;

    for (int t = 0; t < cnt; t++) {
        const uint32_t kb = kbuf[t & 1], eb = ebuf[t & 1];
        CP_WAIT2();                 // K_t (and Q) resident
        __syncthreads();
        if (t + 1 < cnt) load32k(ebuf[(t + 1) & 1], eim + (size_t)(t + 1) * 32768, tid);
        CP_COMMIT();                // E_{t+1} (or empty group)

        // ---- S = Q K^T : warp -> S[16 rows][16 cols @ 16h] ----
        float sacc[2][4];
#pragma unroll
        for (int j = 0; j < 2; j++)
#pragma unroll
            for (int i = 0; i < 4; i++) sacc[j][i] = 0.f;
#pragma unroll 4
        for (int s = 0; s < 32; s++) {
            uint32_t qa[4];
            *(uint4*)qa = *(const uint4*)(smp + (qbase - sb) + (uint32_t)s * 512);
#pragma unroll
            for (int j = 0; j < 2; j++) {
                uint32_t kf[2];
                *(uint2*)kf = *(const uint2*)(smp + (kb - sb) + (uint32_t)s * 1024 + kfoff + j * 256);
                mmat(sacc[j], qa, kf);
            }
        }
        __syncthreads();            // K buffer free
        if (t + 2 < cnt) load32k(kb, kim + (size_t)(t + 2) * 32768, tid);
        CP_COMMIT();                // K_{t+2} (or empty group)

        // ---- exp/mask -> tf32 P (smem) + den ----
        {
            const int r0 = q0 + mblk * 16 + gid, r1 = r0 + 8;
            const int cb = t * 32 + 16 * h + 2 * tig;
#pragma unroll
            for (int j = 0; j < 2; j++) {
                int c0 = cb + 8 * j, c1 = c0 + 1;
                uint32_t t00 = tf32r((c0 <= r0) ? expclip(sacc[j][0]) : 0.f);
                uint32_t t01 = tf32r((c1 <= r0) ? expclip(sacc[j][1]) : 0.f);
                uint32_t t10 = tf32r((c0 <= r1) ? expclip(sacc[j][2]) : 0.f);
                uint32_t t11 = tf32r((c1 <= r1) ? expclip(sacc[j][3]) : 0.f);
                d0 += __uint_as_float(t00) + __uint_as_float(t01);
                d1 += __uint_as_float(t10) + __uint_as_float(t11);
                uint32_t a = SP + (prow * 36 + 16 * h + 8 * j + 2 * tig) * 4;
                *(uint2*)(smp + a) = make_uint2(t00, t01);
                *(uint2*)(smp + a + 8 * 36 * 4) = make_uint2(t10, t11);
            }
        }
        CP_WAIT3();                 // E_t resident
        __syncthreads();            // P visible

        // ---- y += P E : warp -> y[16 rows][128 cols @ 128h] ----
#pragma unroll
        for (int s = 0; s < 4; s++) {
            uint32_t pa[4];
            uint32_t pb = (pbase - sb) + (uint32_t)(8 * s) * 4;
            pa[0] = *(const uint32_t*)(smp + pb);
            pa[1] = *(const uint32_t*)(smp + pb + 8 * 36 * 4);
            pa[2] = *(const uint32_t*)(smp + pb + 16);
            pa[3] = *(const uint32_t*)(smp + pb + 8 * 36 * 4 + 16);
#pragma unroll
            for (int ntl = 0; ntl < 16; ntl++) {
                uint32_t ef[2];
                *(uint2*)ef = *(const uint2*)(smp + (eb - sb) + (uint32_t)s * 8192 + efoff + ntl * 256);
                mmat(yacc[ntl], pa, ef);
            }
        }
    }

    // ---- den reduce ----
    d0 += __shfl_xor_sync(~0u, d0, 1); d0 += __shfl_xor_sync(~0u, d0, 2);
    d1 += __shfl_xor_sync(~0u, d1, 1); d1 += __shfl_xor_sync(~0u, d1, 2);
    if (tig == 0) {
        *(float*)(smp + SDEN + (h * 64 + mblk * 16 + gid) * 4) = d0;
        *(float*)(smp + SDEN + (h * 64 + mblk * 16 + gid + 8) * 4) = d1;
    }
    __syncthreads();                // AV done everywhere; den visible
    float inv0, inv1;
    {
        const float* dn = (const float*)(smp + SDEN);
        int r = mblk * 16 + gid;
        inv0 = 1.f / ((dn[r] + dn[64 + r]) * (float)(q0 + r + 1));
        inv1 = 1.f / ((dn[r + 8] + dn[64 + r + 8]) * (float)(q0 + r + 9));
    }

    // ---- stage ynorm (tf32) into SY [64][260] ----
#pragma unroll
    for (int ntl = 0; ntl < 16; ntl++) {
        uint32_t col = 128 * h + 8 * ntl + 2 * tig;
        uint32_t a = SY + (prow * 260 + col) * 4;
        *(uint2*)(smp + a) = make_uint2(tf32r(yacc[ntl][0] * inv0), tf32r(yacc[ntl][1] * inv0));
        *(uint2*)(smp + a + 8 * 260 * 4) = make_uint2(tf32r(yacc[ntl][2] * inv1), tf32r(yacc[ntl][3] * inv1));
#pragma unroll
        for (int j = 0; j < 4; j++) yacc[ntl][j] = 0.f;
    }
    // W chunk pipeline into the 4 freed buffers
    const uint32_t wbuf[4] = { sb + SK0, sb + SK1, sb + SE0, sb + SE1 };
    load32k(wbuf[0], g_wimg, tid); CP_COMMIT();
    load32k(wbuf[1], g_wimg + 32768, tid); CP_COMMIT();
    load32k(wbuf[2], g_wimg + 2 * 32768, tid); CP_COMMIT();
    load32k(wbuf[3], g_wimg + 3 * 32768, tid); CP_COMMIT();
    __syncthreads();                // ynorm visible

    // ---- epilogue: out = ynorm @ W2 ----
#pragma unroll 1
    for (int c = 0; c < 8; c++) {
        CP_WAIT3();
        __syncthreads();
        const uint32_t wb = wbuf[c & 3];
#pragma unroll
        for (int s = 0; s < 4; s++) {
            uint32_t ya[4];
            uint32_t yb = SY + (prow * 260 + 32 * c + 8 * s + tig) * 4;
            ya[0] = *(const uint32_t*)(smp + yb);
            ya[1] = *(const uint32_t*)(smp + yb + 8 * 260 * 4);
            ya[2] = *(const uint32_t*)(smp + yb + 16);
            ya[3] = *(const uint32_t*)(smp + yb + 8 * 260 * 4 + 16);
#pragma unroll
            for (int ntl = 0; ntl < 16; ntl++) {
                uint32_t wf[2];
                *(uint2*)wf = *(const uint2*)(smp + (wb - sb) + (uint32_t)s * 8192 + efoff + ntl * 256);
                mmat(yacc[ntl], ya, wf);
            }
        }
        __syncthreads();            // buffer free
        if (c + 4 < 8) load32k(wb, g_wimg + (size_t)(c + 4) * 32768, tid);
        CP_COMMIT();                // real or empty group
    }

    // ---- store ----
    {
        const int orow = q0 + mblk * 16 + gid;
        float* ob = out + ((size_t)b * Ss + orow) * Dh;
#pragma unroll
        for (int ntl = 0; ntl < 16; ntl++) {
            int col = 128 * h + 8 * ntl + 2 * tig;
            *(float2*)(ob + col) = make_float2(yacc[ntl][0], yacc[ntl][1]);
            *(float2*)(ob + 8 * Dh + col) = make_float2(yacc[ntl][2], yacc[ntl][3]);
        }
    }
}

extern "C" void kernel_launch(void* const* d_in, const int* in_sizes, int n_in,
                              void* d_out, int out_size) {
    const float* e   = (const float*)d_in[0];
    const float* p   = (const float*)d_in[1];
    const float* W_o = (const float*)d_in[2];
    float* out = (float*)d_out;

    cudaFuncSetAttribute(attn_kernel, cudaFuncAttributeMaxDynamicSharedMemorySize, SMEM_BYTES);

    wt_kernel<<<256, 256>>>(W_o);
    qimg_kernel<<<dim3(32, 8), 256>>>(p);
    kimg_kernel<<<dim3(64, 8), 256>>>(p);
    eimg_kernel<<<dim3(64, 8), 256>>>(e);
    wimg_kernel<<<8, 256>>>();
    attn_kernel<<<dim3(32, 8), 256, SMEM_BYTES>>>(out);
}

// round 10
// speedup vs baseline: 1.2159x; 1.2159x over previous
#include <cuda_runtime.h>
#include <stdint.h>

#define Ss 2048
#define Dh 256

__device__ float g_W2[256 * 256];
__device__ __align__(16) unsigned char g_qimg[8 * 64 * 32768];  // A-frag images, 32-row q-tiles
__device__ __align__(16) unsigned char g_kimg[8 * 64 * 32768];  // B-frag images, 32-key tiles
__device__ __align__(16) unsigned char g_eimg[8 * 64 * 32768];  // B-frag images, 32-key tiles
__device__ __align__(16) unsigned char g_wimg[8 * 32768];       // B-frag images, 32-j chunks

// ---------------- helpers ----------------
__device__ __forceinline__ uint32_t smem_u32(const void* p) {
    uint32_t a; asm("{.reg .u64 t; cvta.to.shared.u64 t,%1; cvt.u32.u64 %0,t;}" : "=r"(a) : "l"(p)); return a;
}
__device__ __forceinline__ uint32_t tf32r(float x) {
    uint32_t r; asm("cvt.rna.tf32.f32 %0,%1;" : "=r"(r) : "f"(x)); return r;
}
__device__ __forceinline__ void mmat(float* c, const uint32_t* a, const uint32_t* b) {
    asm volatile("mma.sync.aligned.m16n8k8.row.col.f32.tf32.tf32.f32 "
        "{%0,%1,%2,%3},{%4,%5,%6,%7},{%8,%9},{%0,%1,%2,%3};"
        : "+f"(c[0]), "+f"(c[1]), "+f"(c[2]), "+f"(c[3])
        : "r"(a[0]), "r"(a[1]), "r"(a[2]), "r"(a[3]), "r"(b[0]), "r"(b[1]));
}
__device__ __forceinline__ float expclip(float s) {
    return __expf(fminf(fmaxf(s * 0.0625f, -10.f), 10.f));
}
__device__ __forceinline__ void cpa16(uint32_t dst, const void* src) {
    asm volatile("cp.async.cg.shared.global [%0],[%1],16;" :: "r"(dst), "l"(src));
}
#define CP_COMMIT() asm volatile("cp.async.commit_group;" ::: "memory")
#define CP_WAIT1()  asm volatile("cp.async.wait_group 1;" ::: "memory")

__device__ __forceinline__ void load32k(uint32_t dst, const unsigned char* src, int tid) {
#pragma unroll
    for (int i = 0; i < 16; i++)
        cpa16(dst + (uint32_t)(tid + 128 * i) * 16, src + (size_t)(tid + 128 * i) * 16);
}

// ---------------- prologue kernels ----------------
__global__ void wt_kernel(const float* __restrict__ W_o) {
    int j = blockIdx.x, dout = threadIdx.x;
    float s = 0.f;
#pragma unroll
    for (int h = 0; h < 8; h++) s += W_o[(size_t)dout * 2048 + h * 256 + j];
    g_W2[j * 256 + dout] = s;
}
// Q: A-frag image per 32-row q-tile: [mblk 0..1][s 0..31][lane][4]
__global__ void qimg_kernel(const float* __restrict__ p) {
    int qt = blockIdx.x, b = blockIdx.y, tid = threadIdx.x;
    const float* P = p + (size_t)b * (Ss + 1) * Dh;
    uint4* dst = (uint4*)(g_qimg + (size_t)(b * 64 + qt) * 32768);
#pragma unroll
    for (int it = 0; it < 8; it++) {
        int idx = tid + 256 * it;
        int mblk = idx >> 10, rem = idx & 1023, s = rem >> 5, l = rem & 31;
        int r = qt * 32 + mblk * 16 + (l >> 2) + 1;   // +1: q = p[:,1:,:]
        int c = 8 * s + (l & 3);
        uint4 v;
        v.x = tf32r(P[(size_t)r * Dh + c]);
        v.y = tf32r(P[(size_t)(r + 8) * Dh + c]);
        v.z = tf32r(P[(size_t)r * Dh + c + 4]);
        v.w = tf32r(P[(size_t)(r + 8) * Dh + c + 4]);
        dst[idx] = v;
    }
}
// K: B-frag image per 32-key tile: [s 0..31][nt 0..3][lane][2]   (k-dim = d)
__global__ void kimg_kernel(const float* __restrict__ p) {
    int kt = blockIdx.x, b = blockIdx.y, tid = threadIdx.x;
    const float* P = p + (size_t)b * (Ss + 1) * Dh;
    uint2* dst = (uint2*)(g_kimg + (size_t)(b * 64 + kt) * 32768);
#pragma unroll
    for (int it = 0; it < 16; it++) {
        int idx = tid + 256 * it;
        int s = idx >> 7, rem = idx & 127, nt = rem >> 5, l = rem & 31;
        int key = kt * 32 + nt * 8 + (l >> 2);
        int d = 8 * s + (l & 3);
        dst[idx] = make_uint2(tf32r(P[(size_t)key * Dh + d]), tf32r(P[(size_t)key * Dh + d + 4]));
    }
}
// E: B-frag image per 32-key tile: [s 0..3][nt 0..31][lane][2]   (k-dim = key)
__global__ void eimg_kernel(const float* __restrict__ e) {
    int kt = blockIdx.x, b = blockIdx.y, tid = threadIdx.x;
    const float* E = e + (size_t)b * Ss * Dh;
    uint2* dst = (uint2*)(g_eimg + (size_t)(b * 64 + kt) * 32768);
#pragma unroll
    for (int it = 0; it < 16; it++) {
        int idx = tid + 256 * it;
        int s = idx >> 10, rem = idx & 1023, nt = rem >> 5, l = rem & 31;
        int key = kt * 32 + 8 * s + (l & 3);
        int n = nt * 8 + (l >> 2);
        dst[idx] = make_uint2(tf32r(E[(size_t)key * Dh + n]), tf32r(E[(size_t)(key + 4) * Dh + n]));
    }
}
// W: B-frag image per 32-j chunk: [s 0..3][nt 0..31][lane][2]   (k-dim = j)
__global__ void wimg_kernel() {
    int ch = blockIdx.x, tid = threadIdx.x;
    uint2* dst = (uint2*)(g_wimg + (size_t)ch * 32768);
#pragma unroll
    for (int it = 0; it < 16; it++) {
        int idx = tid + 256 * it;
        int s = idx >> 10, rem = idx & 1023, nt = rem >> 5, l = rem & 31;
        int j = 32 * ch + 8 * s + (l & 3);
        int n = nt * 8 + (l >> 2);
        dst[idx] = make_uint2(tf32r(g_W2[j * 256 + n]), tf32r(g_W2[(j + 4) * 256 + n]));
    }
}

// ---------------- main kernel ----------------
// smem layout (bytes); ynorm [32][260] f32 (33280) overlays SQ+SP after the loop
#define SQ   0u        // Q image, 32768
#define SP   32768u    // P [32 rows][36 f32] = 4608
#define SK   37376u    // K tile image, 32768
#define SE   70144u    // E tile image, 32768
#define SDEN 102912u   // [2][32] f32
#define SMEM_BYTES 103168u

__global__ __launch_bounds__(128, 2) void attn_kernel(float* __restrict__ out) {
    extern __shared__ unsigned char smp[];
    const uint32_t sb = smem_u32(smp);
    const int tid = threadIdx.x, w = tid >> 5, l = tid & 31;
    const int tig = l & 3, gid = l >> 2;
    const int qt = 63 - (int)blockIdx.x, b = blockIdx.y;
    const int q0 = qt * 32, cnt = qt + 1;
    const int mblk = w & 1, h = w >> 1;

    const unsigned char* kim = g_kimg + (size_t)(b * 64) * 32768;
    const unsigned char* eim = g_eimg + (size_t)(b * 64) * 32768;

    // prologue loads: [Q + K0], [E0]
    load32k(sb + SQ, g_qimg + (size_t)(b * 64 + qt) * 32768, tid);
    load32k(sb + SK, kim, tid);
    CP_COMMIT();
    load32k(sb + SE, eim, tid);
    CP_COMMIT();

    // per-warp address bases
    const uint32_t qbase = (uint32_t)(mblk * 16384) + l * 16;      // + s*512
    const uint32_t kfoff = (uint32_t)(2 * h) * 256 + l * 8;        // + s*1024 + j*256
    const uint32_t efoff = (uint32_t)(16 * h) * 256 + l * 8;       // + s*8192 + ntl*256
    const uint32_t prow = (uint32_t)(mblk * 16 + gid);
    const uint32_t pbase = SP + (prow * 36 + tig) * 4;             // + 8s*4

    float yacc[16][4];
#pragma unroll
    for (int nt = 0; nt < 16; nt++)
#pragma unroll
        for (int j = 0; j < 4; j++) yacc[nt][j] = 0.f;
    float d0 = 0.f, d1 = 0.f;

    for (int t = 0; t < cnt; t++) {
        CP_WAIT1();                 // Q + K_t resident (E_t may be in flight)
        __syncthreads();

        // ---- S = Q K^T : warp -> S[16 rows @ 16mblk][16 cols @ 16h] ----
        float sacc[2][4];
#pragma unroll
        for (int j = 0; j < 2; j++)
#pragma unroll
            for (int i = 0; i < 4; i++) sacc[j][i] = 0.f;
#pragma unroll 4
        for (int s = 0; s < 32; s++) {
            uint32_t qa[4];
            *(uint4*)qa = *(const uint4*)(smp + SQ + qbase + (uint32_t)s * 512);
#pragma unroll
            for (int j = 0; j < 2; j++) {
                uint32_t kf[2];
                *(uint2*)kf = *(const uint2*)(smp + SK + (uint32_t)s * 1024 + kfoff + j * 256);
                mmat(sacc[j], qa, kf);
            }
        }
        __syncthreads();            // K buffer readers done
        if (t + 1 < cnt) load32k(sb + SK, kim + (size_t)(t + 1) * 32768, tid);
        CP_COMMIT();                // K_{t+1} (or empty) -- overlaps exp + AV

        // ---- exp/mask -> tf32 P (smem) + den ----
        {
            const int r0 = q0 + mblk * 16 + gid, r1 = r0 + 8;
            const int cb = t * 32 + 16 * h + 2 * tig;
#pragma unroll
            for (int j = 0; j < 2; j++) {
                int c0 = cb + 8 * j, c1 = c0 + 1;
                uint32_t t00 = tf32r((c0 <= r0) ? expclip(sacc[j][0]) : 0.f);
                uint32_t t01 = tf32r((c1 <= r0) ? expclip(sacc[j][1]) : 0.f);
                uint32_t t10 = tf32r((c0 <= r1) ? expclip(sacc[j][2]) : 0.f);
                uint32_t t11 = tf32r((c1 <= r1) ? expclip(sacc[j][3]) : 0.f);
                d0 += __uint_as_float(t00) + __uint_as_float(t01);
                d1 += __uint_as_float(t10) + __uint_as_float(t11);
                uint32_t a = SP + (prow * 36 + 16 * h + 8 * j + 2 * tig) * 4;
                *(uint2*)(smp + a) = make_uint2(t00, t01);
                *(uint2*)(smp + a + 8 * 36 * 4) = make_uint2(t10, t11);
            }
        }
        CP_WAIT1();                 // E_t resident (K_{t+1} still in flight)
        __syncthreads();            // P visible

        // ---- y += P E : warp -> y[16 rows][128 cols @ 128h] ----
#pragma unroll
        for (int s = 0; s < 4; s++) {
            uint32_t pa[4];
            uint32_t pb = pbase + (uint32_t)(8 * s) * 4;
            pa[0] = *(const uint32_t*)(smp + pb);
            pa[1] = *(const uint32_t*)(smp + pb + 8 * 36 * 4);
            pa[2] = *(const uint32_t*)(smp + pb + 16);
            pa[3] = *(const uint32_t*)(smp + pb + 8 * 36 * 4 + 16);
#pragma unroll
            for (int ntl = 0; ntl < 16; ntl++) {
                uint32_t ef[2];
                *(uint2*)ef = *(const uint2*)(smp + SE + (uint32_t)s * 8192 + efoff + ntl * 256);
                mmat(yacc[ntl], pa, ef);
            }
        }
        __syncthreads();            // E buffer readers done
        if (t + 1 < cnt) load32k(sb + SE, eim + (size_t)(t + 1) * 32768, tid);
        CP_COMMIT();                // E_{t+1} (or empty) -- overlaps next QK
    }

    // ---- den reduce ----
    d0 += __shfl_xor_sync(~0u, d0, 1); d0 += __shfl_xor_sync(~0u, d0, 2);
    d1 += __shfl_xor_sync(~0u, d1, 1); d1 += __shfl_xor_sync(~0u, d1, 2);
    if (tig == 0) {
        *(float*)(smp + SDEN + (h * 32 + mblk * 16 + gid) * 4) = d0;
        *(float*)(smp + SDEN + (h * 32 + mblk * 16 + gid + 8) * 4) = d1;
    }
    __syncthreads();
    float inv0, inv1;
    {
        const float* dn = (const float*)(smp + SDEN);
        int r = mblk * 16 + gid;
        inv0 = 1.f / ((dn[r] + dn[32 + r]) * (float)(q0 + r + 1));
        inv1 = 1.f / ((dn[r + 8] + dn[32 + r + 8]) * (float)(q0 + r + 9));
    }

    // start W pipeline into freed K/E buffers
    load32k(sb + SK, g_wimg, tid); CP_COMMIT();
    load32k(sb + SE, g_wimg + 32768, tid); CP_COMMIT();

    // ---- stage ynorm (tf32) into [32][260] over SQ+SP ----
#pragma unroll
    for (int ntl = 0; ntl < 16; ntl++) {
        uint32_t col = 128 * h + 8 * ntl + 2 * tig;
        uint32_t a = (prow * 260 + col) * 4;
        *(uint2*)(smp + a) = make_uint2(tf32r(yacc[ntl][0] * inv0), tf32r(yacc[ntl][1] * inv0));
        *(uint2*)(smp + a + 8 * 260 * 4) = make_uint2(tf32r(yacc[ntl][2] * inv1), tf32r(yacc[ntl][3] * inv1));
#pragma unroll
        for (int j = 0; j < 4; j++) yacc[ntl][j] = 0.f;
    }
    __syncthreads();                // ynorm visible

    // ---- epilogue: out = ynorm @ W2 (8 chunks of 32 j) ----
#pragma unroll 1
    for (int c = 0; c < 8; c++) {
        CP_WAIT1();
        __syncthreads();
        const uint32_t wb = (c & 1) ? SE : SK;
#pragma unroll
        for (int s = 0; s < 4; s++) {
            uint32_t ya[4];
            uint32_t yb = (prow * 260 + 32 * c + 8 * s + tig) * 4;
            ya[0] = *(const uint32_t*)(smp + yb);
            ya[1] = *(const uint32_t*)(smp + yb + 8 * 260 * 4);
            ya[2] = *(const uint32_t*)(smp + yb + 16);
            ya[3] = *(const uint32_t*)(smp + yb + 8 * 260 * 4 + 16);
#pragma unroll
            for (int ntl = 0; ntl < 16; ntl++) {
                uint32_t wf[2];
                *(uint2*)wf = *(const uint2*)(smp + wb + (uint32_t)s * 8192 + efoff + ntl * 256);
                mmat(yacc[ntl], ya, wf);
            }
        }
        __syncthreads();            // buffer readers done
        if (c + 2 < 8) load32k(sb + ((c & 1) ? SE : SK), g_wimg + (size_t)(c + 2) * 32768, tid);
        CP_COMMIT();                // real or empty group
    }

    // ---- store ----
    {
        const int orow = q0 + mblk * 16 + gid;
        float* ob = out + ((size_t)b * Ss + orow) * Dh;
#pragma unroll
        for (int ntl = 0; ntl < 16; ntl++) {
            int col = 128 * h + 8 * ntl + 2 * tig;
            *(float2*)(ob + col) = make_float2(yacc[ntl][0], yacc[ntl][1]);
            *(float2*)(ob + 8 * Dh + col) = make_float2(yacc[ntl][2], yacc[ntl][3]);
        }
    }
}

extern "C" void kernel_launch(void* const* d_in, const int* in_sizes, int n_in,
                              void* d_out, int out_size) {
    const float* e   = (const float*)d_in[0];
    const float* p   = (const float*)d_in[1];
    const float* W_o = (const float*)d_in[2];
    float* out = (float*)d_out;

    cudaFuncSetAttribute(attn_kernel, cudaFuncAttributeMaxDynamicSharedMemorySize, SMEM_BYTES);

    wt_kernel<<<256, 256>>>(W_o);
    qimg_kernel<<<dim3(64, 8), 256>>>(p);
    kimg_kernel<<<dim3(64, 8), 256>>>(p);
    eimg_kernel<<<dim3(64, 8), 256>>>(e);
    wimg_kernel<<<8, 256>>>();
    attn_kernel<<<dim3(64, 8), 128, SMEM_BYTES>>>(out);
}